// round 9
// baseline (speedup 1.0000x reference)
#include <cuda_runtime.h>
#include <math.h>

// GridPostProcessor (R=50000), fused single kernel:
//   grid_logits: (R, 9, 28, 28) f32 -> per (r,c) max+argmax over 784
//   det_bboxes : (R, 4) f32
//   out        : (R, 4) f32
// One block per row, 9 warps = 9 channels. Per lane: 6 unconditional +
// 1 predicated float4 loads, value-only FMNMX max tree + shfl_xor reduce,
// then equality re-scan on in-register values for the first-occurrence index
// (pred-as-data SEL/IMNMX, no guard-predicate chains).
// launch_bounds(288, 6): regs <= 37 -> 6 blocks/SM (was 5 at regs=40); the
// compute path is now lean enough that extra warps buy DRAM duty cycle.

#define HALF 28
#define HW   (HALF * HALF)     // 784
#define CH   9

__global__ __launch_bounds__(288, 6) void grid_post_fused(
    const float* __restrict__ logits,
    const float* __restrict__ bboxes,
    float* __restrict__ out,
    int R)
{
    const int r    = blockIdx.x;
    const int warp = threadIdx.x >> 5;   // channel
    const int lane = threadIdx.x & 31;

    __shared__ float2 s_mi[CH];          // (max, idx-as-float)
    __shared__ float  s_sc[CH], s_ax[CH], s_ay[CH];
    __shared__ float4 s_bb;

    // ---- loads: streaming, fully unrolled, front-batched ----
    const float4* __restrict__ base =
        (const float4*)(logits + ((size_t)r * CH + warp) * HW);

    float4 v[7];
#pragma unroll
    for (int k = 0; k < 6; k++) v[k] = __ldcs(&base[lane + 32 * k]);
    v[6] = make_float4(-INFINITY, -INFINITY, -INFINITY, -INFINITY);
    if (lane < 4) v[6] = __ldcs(&base[192 + lane]);

    // ---- phase 1: value-only max (FMNMX tree, lat-4 data path) ----
    float pm[7];
#pragma unroll
    for (int k = 0; k < 7; k++)
        pm[k] = fmaxf(fmaxf(v[k].x, v[k].y), fmaxf(v[k].z, v[k].w));
    float m = fmaxf(fmaxf(fmaxf(pm[0], pm[1]), fmaxf(pm[2], pm[3])),
                    fmaxf(fmaxf(pm[4], pm[5]), pm[6]));
#pragma unroll
    for (int off = 16; off > 0; off >>= 1)
        m = fmaxf(m, __shfl_xor_sync(0xffffffffu, m, off));
    // every lane now holds the channel-wide max m

    // ---- phase 2: first-occurrence index of m (pred-as-data select/min) ----
    int loc = 0x7FFFFFFF;
#pragma unroll
    for (int k = 0; k < 7; k++) {
        int vec = (k < 6) ? (lane + 32 * k) : (192 + lane);
        int e   = vec << 2;
        int cx = (v[k].x == m) ? (e + 0) : 0x7FFFFFFF;
        int cy = (v[k].y == m) ? (e + 1) : 0x7FFFFFFF;
        int cz = (v[k].z == m) ? (e + 2) : 0x7FFFFFFF;
        int cw = (v[k].w == m) ? (e + 3) : 0x7FFFFFFF;
        loc = min(loc, min(min(cx, cy), min(cz, cw)));
    }
#pragma unroll
    for (int off = 16; off > 0; off >>= 1)
        loc = min(loc, __shfl_xor_sync(0xffffffffu, loc, off));

    if (lane == 0) s_mi[warp] = make_float2(m, __int_as_float(loc));

    // Prefetch bboxes before the barrier: latency overlaps warp drain.
    if (warp == 0 && lane == 0) s_bb = __ldg(&((const float4*)bboxes)[r]);
    __syncthreads();

    // ---- epilogue: warp 0 only ----
    if (warp == 0) {
        // sub-region offsets (GRID_SIZE=3, WHOLE_MAP=56): 0, 14, 28
        const int sub_x[CH] = {0, 14, 28, 0, 14, 28, 0, 14, 28};
        const int sub_y[CH] = {0, 0, 0, 14, 14, 14, 28, 28, 28};

        const float4 bb = s_bb;
        const float width  = bb.z - bb.x;
        const float height = bb.w - bb.y;
        const float x1 = bb.x - 0.5f * width;    // MAPPING_RATIO = 1
        const float y1 = bb.y - 0.5f * height;
        const float wk = width  * (1.0f / 28.0f);
        const float hk = height * (1.0f / 28.0f);

        if (lane < CH) {
            float2 mi = s_mi[lane];
            int id = __float_as_int(mi.y);
            s_sc[lane] = 1.0f / (1.0f + __expf(-mi.x));
            int xs = (id % HALF) + sub_x[lane];
            int ys = (id / HALF) + sub_y[lane];
            s_ax[lane] = ((float)xs + 0.5f) * wk + x1;
            s_ay[lane] = ((float)ys + 0.5f) * hk + y1;
        }
        __syncwarp();

        if (lane < 4) {
            // out0 (bx1): x over {0,1,2}; out1 (by1): y over {0,3,6}
            // out2 (bx2): x over {6,7,8}; out3 (by2): y over {2,5,8}
            const int e0[4] = {0, 0, 6, 2};
            const int e1[4] = {1, 3, 7, 5};
            const int e2[4] = {2, 6, 8, 8};
            int c0 = e0[lane], c1 = e1[lane], c2 = e2[lane];
            const float* coord = (lane & 1) ? s_ay : s_ax;
            float num = coord[c0] * s_sc[c0] + coord[c1] * s_sc[c1] + coord[c2] * s_sc[c2];
            float den = s_sc[c0] + s_sc[c1] + s_sc[c2];
            out[r * 4 + lane] = num / den;
        }
    }
}

extern "C" void kernel_launch(void* const* d_in, const int* in_sizes, int n_in,
                              void* d_out, int out_size) {
    const float* logits = (const float*)d_in[0];   // (R, 9, 28, 28)
    const float* bboxes = (const float*)d_in[1];   // (R, 4)
    float* out = (float*)d_out;                    // (R, 4)

    int R = in_sizes[0] / (CH * HW);               // 50000

    grid_post_fused<<<R, 288>>>(logits, bboxes, out, R);
}

// round 10
// speedup vs baseline: 1.0287x; 1.0287x over previous
#include <cuda_runtime.h>
#include <math.h>

// GridPostProcessor (R=50000), fused single kernel:
//   grid_logits: (R, 9, 28, 28) f32 -> per (r,c) max+argmax over 784
//   det_bboxes : (R, 4) f32
//   out        : (R, 4) f32
// One block per row, 9 warps = 9 channels. Per lane: 6 unconditional +
// 1 predicated float4 loads, value-only FMNMX max tree + shfl_xor reduce,
// then equality re-scan on in-register values for the first-occurrence index
// (pred-as-data SEL/IMNMX, no guard-predicate chains).
//
// launch_bounds(288, 5): the 28-reg float4 payload (MLP=7 front-batched
// loads) must stay register-resident — forcing 6 blocks/SM (regs<=37)
// spills it (R9: L1 33->46%, DRAM 88.5->81.3%, 195.5->219.9us). 5 blocks
// allows up to 45 regs: no spill, plus scheduling slack over natural 40.

#define HALF 28
#define HW   (HALF * HALF)     // 784
#define CH   9

__global__ __launch_bounds__(288, 5) void grid_post_fused(
    const float* __restrict__ logits,
    const float* __restrict__ bboxes,
    float* __restrict__ out,
    int R)
{
    const int r    = blockIdx.x;
    const int warp = threadIdx.x >> 5;   // channel
    const int lane = threadIdx.x & 31;

    __shared__ float2 s_mi[CH];          // (max, idx-as-float)
    __shared__ float  s_sc[CH], s_ax[CH], s_ay[CH];
    __shared__ float4 s_bb;

    // ---- loads: streaming, fully unrolled, front-batched ----
    const float4* __restrict__ base =
        (const float4*)(logits + ((size_t)r * CH + warp) * HW);

    float4 v[7];
#pragma unroll
    for (int k = 0; k < 6; k++) v[k] = __ldcs(&base[lane + 32 * k]);
    v[6] = make_float4(-INFINITY, -INFINITY, -INFINITY, -INFINITY);
    if (lane < 4) v[6] = __ldcs(&base[192 + lane]);

    // ---- phase 1: value-only max (FMNMX tree, lat-4 data path) ----
    float pm[7];
#pragma unroll
    for (int k = 0; k < 7; k++)
        pm[k] = fmaxf(fmaxf(v[k].x, v[k].y), fmaxf(v[k].z, v[k].w));
    float m = fmaxf(fmaxf(fmaxf(pm[0], pm[1]), fmaxf(pm[2], pm[3])),
                    fmaxf(fmaxf(pm[4], pm[5]), pm[6]));
#pragma unroll
    for (int off = 16; off > 0; off >>= 1)
        m = fmaxf(m, __shfl_xor_sync(0xffffffffu, m, off));
    // every lane now holds the channel-wide max m

    // ---- phase 2: first-occurrence index of m (pred-as-data select/min) ----
    int loc = 0x7FFFFFFF;
#pragma unroll
    for (int k = 0; k < 7; k++) {
        int vec = (k < 6) ? (lane + 32 * k) : (192 + lane);
        int e   = vec << 2;
        int cx = (v[k].x == m) ? (e + 0) : 0x7FFFFFFF;
        int cy = (v[k].y == m) ? (e + 1) : 0x7FFFFFFF;
        int cz = (v[k].z == m) ? (e + 2) : 0x7FFFFFFF;
        int cw = (v[k].w == m) ? (e + 3) : 0x7FFFFFFF;
        loc = min(loc, min(min(cx, cy), min(cz, cw)));
    }
#pragma unroll
    for (int off = 16; off > 0; off >>= 1)
        loc = min(loc, __shfl_xor_sync(0xffffffffu, loc, off));

    if (lane == 0) s_mi[warp] = make_float2(m, __int_as_float(loc));

    // Prefetch bboxes before the barrier: latency overlaps warp drain.
    if (warp == 0 && lane == 0) s_bb = __ldg(&((const float4*)bboxes)[r]);
    __syncthreads();

    // ---- epilogue: warp 0 only ----
    if (warp == 0) {
        // sub-region offsets (GRID_SIZE=3, WHOLE_MAP=56): 0, 14, 28
        const int sub_x[CH] = {0, 14, 28, 0, 14, 28, 0, 14, 28};
        const int sub_y[CH] = {0, 0, 0, 14, 14, 14, 28, 28, 28};

        const float4 bb = s_bb;
        const float width  = bb.z - bb.x;
        const float height = bb.w - bb.y;
        const float x1 = bb.x - 0.5f * width;    // MAPPING_RATIO = 1
        const float y1 = bb.y - 0.5f * height;
        const float wk = width  * (1.0f / 28.0f);
        const float hk = height * (1.0f / 28.0f);

        if (lane < CH) {
            float2 mi = s_mi[lane];
            int id = __float_as_int(mi.y);
            s_sc[lane] = 1.0f / (1.0f + __expf(-mi.x));
            int xs = (id % HALF) + sub_x[lane];
            int ys = (id / HALF) + sub_y[lane];
            s_ax[lane] = ((float)xs + 0.5f) * wk + x1;
            s_ay[lane] = ((float)ys + 0.5f) * hk + y1;
        }
        __syncwarp();

        if (lane < 4) {
            // out0 (bx1): x over {0,1,2}; out1 (by1): y over {0,3,6}
            // out2 (bx2): x over {6,7,8}; out3 (by2): y over {2,5,8}
            const int e0[4] = {0, 0, 6, 2};
            const int e1[4] = {1, 3, 7, 5};
            const int e2[4] = {2, 6, 8, 8};
            int c0 = e0[lane], c1 = e1[lane], c2 = e2[lane];
            const float* coord = (lane & 1) ? s_ay : s_ax;
            float num = coord[c0] * s_sc[c0] + coord[c1] * s_sc[c1] + coord[c2] * s_sc[c2];
            float den = s_sc[c0] + s_sc[c1] + s_sc[c2];
            out[r * 4 + lane] = num / den;
        }
    }
}

extern "C" void kernel_launch(void* const* d_in, const int* in_sizes, int n_in,
                              void* d_out, int out_size) {
    const float* logits = (const float*)d_in[0];   // (R, 9, 28, 28)
    const float* bboxes = (const float*)d_in[1];   // (R, 4)
    float* out = (float*)d_out;                    // (R, 4)

    int R = in_sizes[0] / (CH * HW);               // 50000

    grid_post_fused<<<R, 288>>>(logits, bboxes, out, R);
}

// round 13
// speedup vs baseline: 1.1258x; 1.0944x over previous
#include <cuda_runtime.h>
#include <math.h>

// GridPostProcessor (R=50000), fused single kernel:
//   grid_logits: (R, 9, 28, 28) f32 -> per (r,c) max+argmax over 784
//   det_bboxes : (R, 4) f32
//   out        : (R, 4) f32
// One block per row, 9 warps = 9 channels. Per lane: 6 unconditional +
// 1 predicated float4 loads, value-only FMNMX max tree + shfl_xor reduce,
// then equality re-scan on in-register values for the first-occurrence index
// (pred-as-data SEL/IMNMX, no guard-predicate chains).
//
// NOTE: plain __launch_bounds__(288) is load-bearing. Natural build: regs=40,
// 5 blocks/SM, DRAM 88.5%, 195.5us. Both occupancy hints regressed by
// perturbing ptxas code generation, not just residency:
//   (288,6): regs=32, payload spilled (L1 33->46%), 219.9us
//   (288,5): regs=40 but ALU 44->67%, L1 ->51%, 213.8us
// Do not add min-blocks hints to this kernel.

#define HALF 28
#define HW   (HALF * HALF)     // 784
#define CH   9

__global__ __launch_bounds__(288) void grid_post_fused(
    const float* __restrict__ logits,
    const float* __restrict__ bboxes,
    float* __restrict__ out,
    int R)
{
    const int r    = blockIdx.x;
    const int warp = threadIdx.x >> 5;   // channel
    const int lane = threadIdx.x & 31;

    __shared__ float2 s_mi[CH];          // (max, idx-as-float)
    __shared__ float  s_sc[CH], s_ax[CH], s_ay[CH];
    __shared__ float4 s_bb;

    // ---- loads: streaming, fully unrolled, front-batched ----
    const float4* __restrict__ base =
        (const float4*)(logits + ((size_t)r * CH + warp) * HW);

    float4 v[7];
#pragma unroll
    for (int k = 0; k < 6; k++) v[k] = __ldcs(&base[lane + 32 * k]);
    v[6] = make_float4(-INFINITY, -INFINITY, -INFINITY, -INFINITY);
    if (lane < 4) v[6] = __ldcs(&base[192 + lane]);

    // ---- phase 1: value-only max (FMNMX tree, lat-4 data path) ----
    float pm[7];
#pragma unroll
    for (int k = 0; k < 7; k++)
        pm[k] = fmaxf(fmaxf(v[k].x, v[k].y), fmaxf(v[k].z, v[k].w));
    float m = fmaxf(fmaxf(fmaxf(pm[0], pm[1]), fmaxf(pm[2], pm[3])),
                    fmaxf(fmaxf(pm[4], pm[5]), pm[6]));
#pragma unroll
    for (int off = 16; off > 0; off >>= 1)
        m = fmaxf(m, __shfl_xor_sync(0xffffffffu, m, off));
    // every lane now holds the channel-wide max m

    // ---- phase 2: first-occurrence index of m (pred-as-data select/min) ----
    int loc = 0x7FFFFFFF;
#pragma unroll
    for (int k = 0; k < 7; k++) {
        int vec = (k < 6) ? (lane + 32 * k) : (192 + lane);
        int e   = vec << 2;
        int cx = (v[k].x == m) ? (e + 0) : 0x7FFFFFFF;
        int cy = (v[k].y == m) ? (e + 1) : 0x7FFFFFFF;
        int cz = (v[k].z == m) ? (e + 2) : 0x7FFFFFFF;
        int cw = (v[k].w == m) ? (e + 3) : 0x7FFFFFFF;
        loc = min(loc, min(min(cx, cy), min(cz, cw)));
    }
#pragma unroll
    for (int off = 16; off > 0; off >>= 1)
        loc = min(loc, __shfl_xor_sync(0xffffffffu, loc, off));

    if (lane == 0) s_mi[warp] = make_float2(m, __int_as_float(loc));

    // Prefetch bboxes before the barrier: latency overlaps warp drain.
    if (warp == 0 && lane == 0) s_bb = __ldg(&((const float4*)bboxes)[r]);
    __syncthreads();

    // ---- epilogue: warp 0 only ----
    if (warp == 0) {
        // sub-region offsets (GRID_SIZE=3, WHOLE_MAP=56): 0, 14, 28
        const int sub_x[CH] = {0, 14, 28, 0, 14, 28, 0, 14, 28};
        const int sub_y[CH] = {0, 0, 0, 14, 14, 14, 28, 28, 28};

        const float4 bb = s_bb;
        const float width  = bb.z - bb.x;
        const float height = bb.w - bb.y;
        const float x1 = bb.x - 0.5f * width;    // MAPPING_RATIO = 1
        const float y1 = bb.y - 0.5f * height;
        const float wk = width  * (1.0f / 28.0f);
        const float hk = height * (1.0f / 28.0f);

        if (lane < CH) {
            float2 mi = s_mi[lane];
            int id = __float_as_int(mi.y);
            s_sc[lane] = 1.0f / (1.0f + __expf(-mi.x));
            int xs = (id % HALF) + sub_x[lane];
            int ys = (id / HALF) + sub_y[lane];
            s_ax[lane] = ((float)xs + 0.5f) * wk + x1;
            s_ay[lane] = ((float)ys + 0.5f) * hk + y1;
        }
        __syncwarp();

        if (lane < 4) {
            // out0 (bx1): x over {0,1,2}; out1 (by1): y over {0,3,6}
            // out2 (bx2): x over {6,7,8}; out3 (by2): y over {2,5,8}
            const int e0[4] = {0, 0, 6, 2};
            const int e1[4] = {1, 3, 7, 5};
            const int e2[4] = {2, 6, 8, 8};
            int c0 = e0[lane], c1 = e1[lane], c2 = e2[lane];
            const float* coord = (lane & 1) ? s_ay : s_ax;
            float num = coord[c0] * s_sc[c0] + coord[c1] * s_sc[c1] + coord[c2] * s_sc[c2];
            float den = s_sc[c0] + s_sc[c1] + s_sc[c2];
            out[r * 4 + lane] = num / den;
        }
    }
}

extern "C" void kernel_launch(void* const* d_in, const int* in_sizes, int n_in,
                              void* d_out, int out_size) {
    const float* logits = (const float*)d_in[0];   // (R, 9, 28, 28)
    const float* bboxes = (const float*)d_in[1];   // (R, 4)
    float* out = (float*)d_out;                    // (R, 4)

    int R = in_sizes[0] / (CH * HW);               // 50000

    grid_post_fused<<<R, 288>>>(logits, bboxes, out, R);
}

// round 14
// speedup vs baseline: 1.1394x; 1.0121x over previous
#include <cuda_runtime.h>
#include <math.h>

// GridPostProcessor (R=50000), fused single kernel:
//   grid_logits: (R, 9, 28, 28) f32 -> per (r,c) max+argmax over 784
//   det_bboxes : (R, 4) f32
//   out        : (R, 4) f32
// One block per row, 9 warps = 9 channels. Uniform lane mapping: 196 vec4 =
// 28 lanes x 7 loads (vec = k*28 + lane), lanes 28-31 idle with -INF fill.
// Value-only FMNMX max tree + shfl_xor reduce, then equality re-scan on
// in-register values for the first-occurrence index (pred-as-data, no
// guard-predicate chains).
//
// NOTE: plain __launch_bounds__(288) is load-bearing. Natural build: regs=40,
// 5 blocks/SM, DRAM 88.5%, ~195us. Min-blocks hints regress by perturbing
// ptxas code generation:
//   (288,6): regs=32, payload spilled (L1 33->46%), 219.9us
//   (288,5): regs=40 but ALU 44->67%, L1 ->51%, 213.8us
// Do not add min-blocks hints to this kernel.

#define HALF 28
#define HW   (HALF * HALF)     // 784
#define CH   9

__global__ __launch_bounds__(288) void grid_post_fused(
    const float* __restrict__ logits,
    const float* __restrict__ bboxes,
    float* __restrict__ out,
    int R)
{
    const int r    = blockIdx.x;
    const int warp = threadIdx.x >> 5;   // channel
    const int lane = threadIdx.x & 31;

    __shared__ float2 s_mi[CH];          // (max, idx-as-float)
    __shared__ float  s_sc[CH], s_ax[CH], s_ay[CH];
    __shared__ float4 s_bb;

    // bbox prefetch at the very top: joins the front load batch, latency
    // fully covered by the logits stream.
    if (warp == 0 && lane == 0) s_bb = __ldg(&((const float4*)bboxes)[r]);

    // ---- loads: streaming, fully unrolled, uniform 28-lane mapping ----
    const float4* __restrict__ base =
        (const float4*)(logits + ((size_t)r * CH + warp) * HW);

    const bool active = (lane < 28);
    float4 v[7];
#pragma unroll
    for (int k = 0; k < 7; k++) {
        v[k] = make_float4(-INFINITY, -INFINITY, -INFINITY, -INFINITY);
        if (active) v[k] = __ldcs(&base[k * 28 + lane]);
    }

    // ---- phase 1: value-only max (FMNMX tree, lat-4 data path) ----
    float pm[7];
#pragma unroll
    for (int k = 0; k < 7; k++)
        pm[k] = fmaxf(fmaxf(v[k].x, v[k].y), fmaxf(v[k].z, v[k].w));
    float m = fmaxf(fmaxf(fmaxf(pm[0], pm[1]), fmaxf(pm[2], pm[3])),
                    fmaxf(fmaxf(pm[4], pm[5]), pm[6]));
#pragma unroll
    for (int off = 16; off > 0; off >>= 1)
        m = fmaxf(m, __shfl_xor_sync(0xffffffffu, m, off));
    // every lane now holds the channel-wide max m (finite, so idle lanes'
    // -INF never matches in phase 2)

    // ---- phase 2: first-occurrence index of m (pred-as-data select/min) ----
    int loc = 0x7FFFFFFF;
#pragma unroll
    for (int k = 0; k < 7; k++) {
        int e = (k * 28 + lane) << 2;
        int cx = (v[k].x == m) ? (e + 0) : 0x7FFFFFFF;
        int cy = (v[k].y == m) ? (e + 1) : 0x7FFFFFFF;
        int cz = (v[k].z == m) ? (e + 2) : 0x7FFFFFFF;
        int cw = (v[k].w == m) ? (e + 3) : 0x7FFFFFFF;
        loc = min(loc, min(min(cx, cy), min(cz, cw)));
    }
#pragma unroll
    for (int off = 16; off > 0; off >>= 1)
        loc = min(loc, __shfl_xor_sync(0xffffffffu, loc, off));

    if (lane == 0) s_mi[warp] = make_float2(m, __int_as_float(loc));
    __syncthreads();

    // ---- epilogue: warp 0 only ----
    if (warp == 0) {
        // sub-region offsets (GRID_SIZE=3, WHOLE_MAP=56): 0, 14, 28
        const int sub_x[CH] = {0, 14, 28, 0, 14, 28, 0, 14, 28};
        const int sub_y[CH] = {0, 0, 0, 14, 14, 14, 28, 28, 28};

        const float4 bb = s_bb;
        const float width  = bb.z - bb.x;
        const float height = bb.w - bb.y;
        const float x1 = bb.x - 0.5f * width;    // MAPPING_RATIO = 1
        const float y1 = bb.y - 0.5f * height;
        const float wk = width  * (1.0f / 28.0f);
        const float hk = height * (1.0f / 28.0f);

        if (lane < CH) {
            float2 mi = s_mi[lane];
            int id = __float_as_int(mi.y);
            s_sc[lane] = 1.0f / (1.0f + __expf(-mi.x));
            int xs = (id % HALF) + sub_x[lane];
            int ys = (id / HALF) + sub_y[lane];
            s_ax[lane] = ((float)xs + 0.5f) * wk + x1;
            s_ay[lane] = ((float)ys + 0.5f) * hk + y1;
        }
        __syncwarp();

        if (lane < 4) {
            // out0 (bx1): x over {0,1,2}; out1 (by1): y over {0,3,6}
            // out2 (bx2): x over {6,7,8}; out3 (by2): y over {2,5,8}
            const int e0[4] = {0, 0, 6, 2};
            const int e1[4] = {1, 3, 7, 5};
            const int e2[4] = {2, 6, 8, 8};
            int c0 = e0[lane], c1 = e1[lane], c2 = e2[lane];
            const float* coord = (lane & 1) ? s_ay : s_ax;
            float num = coord[c0] * s_sc[c0] + coord[c1] * s_sc[c1] + coord[c2] * s_sc[c2];
            float den = s_sc[c0] + s_sc[c1] + s_sc[c2];
            out[r * 4 + lane] = num / den;
        }
    }
}

extern "C" void kernel_launch(void* const* d_in, const int* in_sizes, int n_in,
                              void* d_out, int out_size) {
    const float* logits = (const float*)d_in[0];   // (R, 9, 28, 28)
    const float* bboxes = (const float*)d_in[1];   // (R, 4)
    float* out = (float*)d_out;                    // (R, 4)

    int R = in_sizes[0] / (CH * HW);               // 50000

    grid_post_fused<<<R, 288>>>(logits, bboxes, out, R);
}